// round 4
// baseline (speedup 1.0000x reference)
#include <cuda_runtime.h>
#include <math.h>

#define C_IN 768
#define DDIM 8
#define LDIM 8
#define NTOK_MAX 65536

#define K1_THREADS 256
#define TILE_TOK 256
#define CHUNK 16
#define ZPITCH 20  // floats; pitch % 8 == 4 -> conflict-free per-lane LDS.128

#define K2_THREADS 192
#define K2_TILE 256

// Scratch (no allocations allowed): duplicated code pairs (c,c) per (token, d)
__device__ unsigned long long g_codes[(size_t)NTOK_MAX * DDIM];
__device__ float g_err;

static __device__ __forceinline__ unsigned long long pack2(float lo, float hi) {
    unsigned long long r;
    asm("mov.b64 %0, {%1, %2};" : "=l"(r) : "f"(lo), "f"(hi));
    return r;
}
static __device__ __forceinline__ void unpack2(unsigned long long v, float& lo, float& hi) {
    asm("mov.b64 {%0, %1}, %2;" : "=f"(lo), "=f"(hi) : "l"(v));
}
// Packed fp32x2 FMA (sm_100+): 2 IEEE fp32 FMAs per instruction.
static __device__ __forceinline__ unsigned long long fma2(unsigned long long a,
                                                          unsigned long long b,
                                                          unsigned long long c) {
    unsigned long long d;
    asm("fma.rn.f32x2 %0, %1, %2, %3;" : "=l"(d) : "l"(a), "l"(b), "l"(c));
    return d;
}

__global__ void k_init() { g_err = 0.0f; }

// Kernel 1: compress GEMV + gumbel argmax + codes + squared-error accumulation.
// Thread-per-token; Wc broadcast from shared; z staged via shared for coalescing.
__global__ void __launch_bounds__(K1_THREADS) k_compress(
    const float* __restrict__ z, const float* __restrict__ u,
    const float* __restrict__ Wc, const float* __restrict__ bc,
    const float* __restrict__ cb, int ntok)
{
    __shared__ __align__(16) float sWc[C_IN * DDIM];      // 24 KB
    __shared__ __align__(16) float sZ[TILE_TOK * ZPITCH]; // 20 KB
    __shared__ float sBC[DDIM];
    __shared__ float sCB[DDIM * LDIM];
    __shared__ float sRed[K1_THREADS / 32];

    const int tid = threadIdx.x;

    for (int i = tid; i < C_IN * DDIM; i += K1_THREADS) sWc[i] = Wc[i];
    if (tid < DDIM) sBC[tid] = bc[tid];
    if (tid < DDIM * LDIM) sCB[tid] = cb[tid];

    const int tok0 = blockIdx.x * TILE_TOK;
    const int mytok = tok0 + tid;

    unsigned long long acc0 = pack2(0.f, 0.f);
    unsigned long long acc1 = acc0, acc2 = acc0, acc3 = acc0;

    const int srow = tid >> 2;         // 0..63
    const int scol = (tid & 3) * 4;    // float4 slot within 16-ch chunk

    for (int c0 = 0; c0 < C_IN; c0 += CHUNK) {
        __syncthreads();  // previous chunk's readers done (also fences weight loads on iter 0)
        // Coalesced stage of z[tok0..tok0+255][c0..c0+15] into shared
        #pragma unroll
        for (int it = 0; it < TILE_TOK / (K1_THREADS / 4); it++) {  // 4 iters
            int row = srow + it * (K1_THREADS / 4);
            int gt = tok0 + row;
            if (gt >= ntok) gt = ntok - 1;
            float4 v = *reinterpret_cast<const float4*>(&z[(size_t)gt * C_IN + c0 + scol]);
            *reinterpret_cast<float4*>(&sZ[row * ZPITCH + scol]) = v;
        }
        __syncthreads();
        // Thread computes its own token's partial zc over this 16-channel chunk
        #pragma unroll
        for (int g = 0; g < CHUNK; g += 4) {
            float4 zv = *reinterpret_cast<const float4*>(&sZ[tid * ZPITCH + g]);
            const ulonglong2* wr =
                reinterpret_cast<const ulonglong2*>(&sWc[(c0 + g) * DDIM]);
            float zk[4] = {zv.x, zv.y, zv.z, zv.w};
            #pragma unroll
            for (int k = 0; k < 4; k++) {
                unsigned long long zz = pack2(zk[k], zk[k]);
                ulonglong2 wa = wr[k * 2 + 0];   // Wc[row][0..3] -> broadcast LDS.128
                ulonglong2 wb = wr[k * 2 + 1];   // Wc[row][4..7]
                acc0 = fma2(zz, wa.x, acc0);
                acc1 = fma2(zz, wa.y, acc1);
                acc2 = fma2(zz, wb.x, acc2);
                acc3 = fma2(zz, wb.y, acc3);
            }
        }
    }

    float zc[DDIM];
    unpack2(acc0, zc[0], zc[1]);
    unpack2(acc1, zc[2], zc[3]);
    unpack2(acc2, zc[4], zc[5]);
    unpack2(acc3, zc[6], zc[7]);
    #pragma unroll
    for (int d = 0; d < DDIM; d++) zc[d] += sBC[d];

    float err = 0.0f;
    if (mytok < ntok) {
        const float4* u4 = reinterpret_cast<const float4*>(u + (size_t)mytok * DDIM * LDIM);
        #pragma unroll
        for (int d = 0; d < DDIM; d++) {
            float4 ua = u4[d * 2 + 0];
            float4 ub = u4[d * 2 + 1];
            float uv[LDIM] = {ua.x, ua.y, ua.z, ua.w, ub.x, ub.y, ub.z, ub.w};
            float best = -INFINITY;
            int bi = 0;
            // argmax over l of gumbel(u) - |zc - cb|  (== argmax of reference softmax;
            // strict > keeps first index on ties, matching jnp.argmax)
            #pragma unroll
            for (int l = 0; l < LDIM; l++) {
                float la = logf(uv[l] + 1e-10f);
                float gmb = -logf(-la);
                float s = gmb - fabsf(zc[d] - sCB[d * LDIM + l]);
                if (s > best) { best = s; bi = l; }
            }
            float code = sCB[d * LDIM + bi];
            float dd = zc[d] - code;
            err += dd * dd;
            g_codes[(size_t)mytok * DDIM + d] = pack2(code, code);
        }
    }

    // Block-reduce squared error, one atomic per block
    #pragma unroll
    for (int o = 16; o > 0; o >>= 1) err += __shfl_down_sync(0xffffffffu, err, o);
    if ((tid & 31) == 0) sRed[tid >> 5] = err;
    __syncthreads();
    if (tid == 0) {
        float t = 0.f;
        #pragma unroll
        for (int w = 0; w < K1_THREADS / 32; w++) t += sRed[w];
        atomicAdd(&g_err, t);
    }
}

// Kernel 2: expand z_q = codes @ We + be.
// Thread owns 4 consecutive channels; We row slices live in registers;
// codes broadcast from shared; perfectly coalesced STG.128.
__global__ void __launch_bounds__(K2_THREADS) k_expand(
    const float* __restrict__ We, const float* __restrict__ be,
    float* __restrict__ out, int ntok)
{
    __shared__ __align__(16) unsigned long long sC[K2_TILE * DDIM];  // 16 KB
    const int tid = threadIdx.x;
    const int c0 = tid * 4;

    ulonglong2 wv[DDIM];
    #pragma unroll
    for (int d = 0; d < DDIM; d++)
        wv[d] = *reinterpret_cast<const ulonglong2*>(&We[d * C_IN + c0]);
    ulonglong2 bev = *reinterpret_cast<const ulonglong2*>(&be[c0]);

    const int tok0 = blockIdx.x * K2_TILE;
    for (int i = tid; i < K2_TILE * DDIM; i += K2_THREADS)
        sC[i] = g_codes[(size_t)tok0 * DDIM + i];
    __syncthreads();

    int tmax = ntok - tok0;
    if (tmax > K2_TILE) tmax = K2_TILE;
    #pragma unroll 2
    for (int t = 0; t < tmax; t++) {
        unsigned long long a0 = bev.x, a1 = bev.y;
        #pragma unroll
        for (int d = 0; d < DDIM; d++) {
            unsigned long long cd = sC[t * DDIM + d];  // broadcast
            a0 = fma2(cd, wv[d].x, a0);
            a1 = fma2(cd, wv[d].y, a1);
        }
        float4 o;
        unpack2(a0, o.x, o.y);
        unpack2(a1, o.z, o.w);
        *reinterpret_cast<float4*>(&out[(size_t)(tok0 + t) * C_IN + c0]) = o;
    }
}

__global__ void k_fin(float* __restrict__ out, long long idx, float inv) {
    out[idx] = g_err * inv;
}

extern "C" void kernel_launch(void* const* d_in, const int* in_sizes, int n_in,
                              void* d_out, int out_size) {
    const float* z  = (const float*)d_in[0];
    const float* u  = (const float*)d_in[1];
    const float* Wc = (const float*)d_in[2];
    const float* bc = (const float*)d_in[3];
    const float* We = (const float*)d_in[4];
    const float* be = (const float*)d_in[5];
    const float* cb = (const float*)d_in[6];
    // d_in[7] = codebook_mask: all-true here (levels == [8]*8), intentionally unused.
    float* out = (float*)d_out;

    const int ntok = in_sizes[0] / C_IN;  // 65536
    const int g1 = (ntok + TILE_TOK - 1) / TILE_TOK;
    const int g2 = (ntok + K2_TILE - 1) / K2_TILE;

    k_init<<<1, 1>>>();
    k_compress<<<g1, K1_THREADS>>>(z, u, Wc, bc, cb, ntok);
    k_expand<<<g2, K2_THREADS>>>(We, be, out, ntok);
    if (out_size > ntok * C_IN) {
        k_fin<<<1, 1>>>(out, (long long)ntok * C_IN,
                        1.0f / ((float)ntok * (float)DDIM));
    }
}